// round 5
// baseline (speedup 1.0000x reference)
#include <cuda_runtime.h>

#define BATCH 128
#define SEQ   512
#define DIM   768
#define MAXC  64
#define NT    64               // 2 independent warps per CTA
#define WARPS_PER_BATCH 32     // each warp -> 2 ranks
#define GRID (BATCH * WARPS_PER_BATCH / 2)

__global__ __launch_bounds__(NT)
void summarizer_kernel(const float* __restrict__ enc,
                       const float* __restrict__ W,
                       const float* __restrict__ bias,
                       const int* __restrict__ cls,
                       float* __restrict__ out) {
    const int lane = threadIdx.x & 31;
    const int warp = threadIdx.x >> 5;
    const int gw   = blockIdx.x * 2 + warp;      // global warp id
    const int b    = gw >> 5;                    // batch (32 warps per batch)
    const int r0   = (gw & 31) * 2;              // first of two ranks this warp owns
    const int r1   = r0 + 1;

    // ---- Phase 1 (warp-local, no barriers): build 16-flag mask per lane ----
    const int4* mp = reinterpret_cast<const int4*>(cls + (size_t)b * SEQ) + lane * 4;
    const int4 c0 = mp[0];
    const int4 c1 = mp[1];
    const int4 c2 = mp[2];
    const int4 c3 = mp[3];

    unsigned m = 0;
    m |= (c0.x != 0) << 0;  m |= (c0.y != 0) << 1;  m |= (c0.z != 0) << 2;  m |= (c0.w != 0) << 3;
    m |= (c1.x != 0) << 4;  m |= (c1.y != 0) << 5;  m |= (c1.z != 0) << 6;  m |= (c1.w != 0) << 7;
    m |= (c2.x != 0) << 8;  m |= (c2.y != 0) << 9;  m |= (c2.z != 0) << 10; m |= (c2.w != 0) << 11;
    m |= (c3.x != 0) << 12; m |= (c3.y != 0) << 13; m |= (c3.z != 0) << 14; m |= (c3.w != 0) << 15;

    const int cnt = __popc(m);
    int s = cnt;
    #pragma unroll
    for (int off = 1; off < 32; off <<= 1) {
        int n = __shfl_up_sync(0xffffffffu, s, off);
        if (lane >= off) s += n;
    }
    const int excl = s - cnt;

    // Extract positions of ranks r0, r1.
    const unsigned ball0 = __ballot_sync(0xffffffffu, r0 >= excl && r0 < excl + cnt);
    const unsigned ball1 = __ballot_sync(0xffffffffu, r1 >= excl && r1 < excl + cnt);
    int j0 = r0 - excl; if (j0 < 0) j0 = 0;
    int j1 = r1 - excl; if (j1 < 0) j1 = 0;
    const int cand0 = lane * 16 + __fns(m, 0, j0 + 1);
    const int cand1 = lane * 16 + __fns(m, 0, j1 + 1);
    const int p0 = ball0 ? __shfl_sync(0xffffffffu, cand0, __ffs(ball0) - 1) : -1;
    const int p1 = ball1 ? __shfl_sync(0xffffffffu, cand1, __ffs(ball1) - 1) : -1;

    const float bv = bias[0];

    if (p0 < 0) {
        // Both ranks invalid (validity is rank-monotone): constant output.
        if (lane == 0) {
            const float v = 1.0f / (1.0f + expf(-bv));
            out[b * MAXC + r0] = v;
            out[b * MAXC + r1] = v;
        }
        return;
    }

    // ---- Phase 2: dot products, all loads front-batched ----
    const float4* __restrict__ w4 = reinterpret_cast<const float4*>(W);
    const float4 w0 = w4[lane +   0];
    const float4 w1 = w4[lane +  32];
    const float4 w2 = w4[lane +  64];
    const float4 w3 = w4[lane +  96];
    const float4 w4v = w4[lane + 128];
    const float4 w5 = w4[lane + 160];

    float s0 = 0.0f, s1 = 0.0f;

    if (p1 >= 0) {
        const float4* ra = reinterpret_cast<const float4*>(enc + ((size_t)b * SEQ + p0) * DIM);
        const float4* rb = reinterpret_cast<const float4*>(enc + ((size_t)b * SEQ + p1) * DIM);
        float4 a0 = ra[lane +   0];
        float4 a1 = ra[lane +  32];
        float4 a2 = ra[lane +  64];
        float4 a3 = ra[lane +  96];
        float4 a4 = ra[lane + 128];
        float4 a5 = ra[lane + 160];
        float4 b0 = rb[lane +   0];
        float4 b1 = rb[lane +  32];
        float4 b2 = rb[lane +  64];
        float4 b3 = rb[lane +  96];
        float4 b4 = rb[lane + 128];
        float4 b5 = rb[lane + 160];
        s0 += a0.x*w0.x + a0.y*w0.y + a0.z*w0.z + a0.w*w0.w;
        s0 += a1.x*w1.x + a1.y*w1.y + a1.z*w1.z + a1.w*w1.w;
        s0 += a2.x*w2.x + a2.y*w2.y + a2.z*w2.z + a2.w*w2.w;
        s0 += a3.x*w3.x + a3.y*w3.y + a3.z*w3.z + a3.w*w3.w;
        s0 += a4.x*w4v.x + a4.y*w4v.y + a4.z*w4v.z + a4.w*w4v.w;
        s0 += a5.x*w5.x + a5.y*w5.y + a5.z*w5.z + a5.w*w5.w;
        s1 += b0.x*w0.x + b0.y*w0.y + b0.z*w0.z + b0.w*w0.w;
        s1 += b1.x*w1.x + b1.y*w1.y + b1.z*w1.z + b1.w*w1.w;
        s1 += b2.x*w2.x + b2.y*w2.y + b2.z*w2.z + b2.w*w2.w;
        s1 += b3.x*w3.x + b3.y*w3.y + b3.z*w3.z + b3.w*w3.w;
        s1 += b4.x*w4v.x + b4.y*w4v.y + b4.z*w4v.z + b4.w*w4v.w;
        s1 += b5.x*w5.x + b5.y*w5.y + b5.z*w5.z + b5.w*w5.w;
    } else {
        const float4* ra = reinterpret_cast<const float4*>(enc + ((size_t)b * SEQ + p0) * DIM);
        float4 a0 = ra[lane +   0];
        float4 a1 = ra[lane +  32];
        float4 a2 = ra[lane +  64];
        float4 a3 = ra[lane +  96];
        float4 a4 = ra[lane + 128];
        float4 a5 = ra[lane + 160];
        s0 += a0.x*w0.x + a0.y*w0.y + a0.z*w0.z + a0.w*w0.w;
        s0 += a1.x*w1.x + a1.y*w1.y + a1.z*w1.z + a1.w*w1.w;
        s0 += a2.x*w2.x + a2.y*w2.y + a2.z*w2.z + a2.w*w2.w;
        s0 += a3.x*w3.x + a3.y*w3.y + a3.z*w3.z + a3.w*w3.w;
        s0 += a4.x*w4v.x + a4.y*w4v.y + a4.z*w4v.z + a4.w*w4v.w;
        s0 += a5.x*w5.x + a5.y*w5.y + a5.z*w5.z + a5.w*w5.w;
    }

    #pragma unroll
    for (int off = 16; off > 0; off >>= 1) {
        s0 += __shfl_down_sync(0xffffffffu, s0, off);
        s1 += __shfl_down_sync(0xffffffffu, s1, off);
    }

    if (lane == 0) {
        out[b * MAXC + r0] = 1.0f / (1.0f + expf(-(s0 + bv)));
        out[b * MAXC + r1] = (p1 >= 0) ? 1.0f / (1.0f + expf(-(s1 + bv)))
                                       : 1.0f / (1.0f + expf(-bv));
    }
}

extern "C" void kernel_launch(void* const* d_in, const int* in_sizes, int n_in,
                              void* d_out, int out_size) {
    const float* enc  = (const float*)d_in[0];
    const float* W    = (const float*)d_in[1];
    const float* bias = (const float*)d_in[2];
    const int*   cls  = (const int*)d_in[3];
    float* out = (float*)d_out;

    summarizer_kernel<<<GRID, NT>>>(enc, W, bias, cls, out);
}